// round 3
// baseline (speedup 1.0000x reference)
#include <cuda_runtime.h>
#include <cuda_bf16.h>
#include <cstdint>

#define NHEADS 16
#define OD     1024
#define KD     128
#define NTOK   4096
#define EDIM   2048
#define TM     128        // tokens per block
#define NC     128        // options per chunk
#define NCHK   (OD/NC)    // 8
#define THETA  6e-3f
#define NEG_INF (-3.402823466e38f)

// ---------------- device scratch (allocation-free rule) ----------------
__device__ __align__(16) __nv_bfloat16 g_wb[(size_t)NHEADS * OD * KD];
__device__ int          g_idx[NTOK * NHEADS];
__device__ unsigned int g_resc_cnt;
__device__ uint2        g_resc[NTOK * NHEADS];

// ---------------- smem layout ----------------
#define SM_X    0                   // 128x128 bf16 blocked SW128 (32KB)
#define SM_W    32768               // two 32KB w buffers
#define SM_TAB  98304               // top3 tables: 5 x 256 x 4B
#define SM_TOTAL (98304 + 5120)

// ---------------- helpers ----------------
__device__ __forceinline__ uint32_t smem_u32(const void* p) {
    uint32_t a;
    asm("{ .reg .u64 t; cvta.to.shared.u64 t, %1; cvt.u32.u64 %0, t; }"
        : "=r"(a) : "l"(p));
    return a;
}

// blocked SW128 atom layout for a [128 rows x 128 bf16] tile.
// c8 = 16B vector index along k (0..15).
__device__ __forceinline__ uint32_t swz(int row, int c8) {
    uint32_t boff = (uint32_t)(((row >> 3) + (c8 >> 3) * 16) * 1024
                               + (row & 7) * 128 + (c8 & 7) * 16);
    return boff ^ ((boff >> 3) & 0x70);
}

#define CP16(dst, src) \
    asm volatile("cp.async.cg.shared.global [%0], [%1], 16;" \
        :: "r"(dst), "l"(src))
#define CPCOMMIT() asm volatile("cp.async.commit_group;" ::: "memory")
#define CPWAIT1()  asm volatile("cp.async.wait_group 1;" ::: "memory")
#define CPWAIT0()  asm volatile("cp.async.wait_group 0;" ::: "memory")

__device__ __forceinline__ void ldm4(uint32_t* r, uint32_t addr) {
    asm volatile("ldmatrix.sync.aligned.m8n8.x4.shared.b16 {%0,%1,%2,%3}, [%4];"
        : "=r"(r[0]), "=r"(r[1]), "=r"(r[2]), "=r"(r[3]) : "r"(addr));
}
__device__ __forceinline__ void mma16816(float* c, const uint32_t* a,
                                         uint32_t b0, uint32_t b1) {
    asm volatile("mma.sync.aligned.m16n8k16.row.col.f32.bf16.bf16.f32 "
        "{%0,%1,%2,%3}, {%4,%5,%6,%7}, {%8,%9}, {%0,%1,%2,%3};"
        : "+f"(c[0]), "+f"(c[1]), "+f"(c[2]), "+f"(c[3])
        : "r"(a[0]), "r"(a[1]), "r"(a[2]), "r"(a[3]), "r"(b0), "r"(b1));
}

// merge top-3 triple b into a (ties -> lower index wins)
__device__ __forceinline__ void merge3(float& a1, float& a2, float& a3, int& j1, int& j2,
                                       float b1, float b2, float b3, int k1, int k2) {
    if (b1 > a1 || (b1 == a1 && k1 < j1)) {
        float t1 = a1, t2 = a2, t3 = a3; int u1 = j1, u2 = j2;
        a1 = b1; a2 = b2; a3 = b3; j1 = k1; j2 = k2;
        b1 = t1; b2 = t2; b3 = t3; k1 = u1; k2 = u2;
    }
    if (b1 > a2 || (b1 == a2 && k1 < j2)) {
        a3 = fmaxf(a2, b2);
        a2 = b1; j2 = k1;
    } else {
        a3 = fmaxf(a3, b1);
    }
}

// ---------------- kernels ----------------

// w fp32 [h][o][k] -> bf16 (same layout); also reset rescue counter
__global__ void convert_w_kernel(const float* __restrict__ w) {
    if (blockIdx.x == 0 && threadIdx.x == 0) g_resc_cnt = 0;
    size_t i = (size_t)blockIdx.x * 256 + threadIdx.x;   // over H*O*K/4 float4s
    float4 v = ((const float4*)w)[i];
    __nv_bfloat162 q0 = __floats2bfloat162_rn(v.x, v.y);
    __nv_bfloat162 q1 = __floats2bfloat162_rn(v.z, v.w);
    uint2 st = make_uint2(*(uint32_t*)&q0, *(uint32_t*)&q1);
    *(uint2*)(g_wb + i * 4) = st;
}

// Main: block = 128 tokens x 1 head. bf16 HMMA GEMM-argmax with top-3 tracking.
__global__ __launch_bounds__(256, 2) void vq_mma_kernel(const float* __restrict__ x) {
    extern __shared__ char smem[];
    const uint32_t sb = smem_u32(smem);
    float* tv1 = (float*)(smem + SM_TAB);
    float* tv2 = tv1 + 256;
    float* tv3 = tv2 + 256;
    int*   ti1 = (int*)(tv3 + 256);
    int*   ti2 = ti1 + 256;

    const int tid = threadIdx.x, l = tid & 31, wid = tid >> 5;
    const int mwarp = wid & 3, nwarp = wid >> 2;
    const int t0 = blockIdx.x * TM, h = blockIdx.y;

    const __nv_bfloat16* wsrc = g_wb + (size_t)h * OD * KD;

    // issue w chunks 0,1 via cp.async (groups 0,1)
#pragma unroll
    for (int buf = 0; buf < 2; buf++) {
        for (int i = tid; i < 2048; i += 256) {
            int row = i >> 4, c8 = i & 15;
            CP16(sb + SM_W + buf * 32768 + swz(row, c8),
                 wsrc + (size_t)(buf * NC + row) * KD + c8 * 8);
        }
        CPCOMMIT();
    }

    // x tile: load fp32, convert to bf16, store swizzled
    for (int i = tid; i < 2048; i += 256) {
        int row = i >> 4, c8 = i & 15;
        const float4* p = (const float4*)(x + (size_t)(t0 + row) * EDIM + h * KD + c8 * 8);
        float4 a = p[0], b = p[1];
        __nv_bfloat162 q0 = __floats2bfloat162_rn(a.x, a.y);
        __nv_bfloat162 q1 = __floats2bfloat162_rn(a.z, a.w);
        __nv_bfloat162 q2 = __floats2bfloat162_rn(b.x, b.y);
        __nv_bfloat162 q3 = __floats2bfloat162_rn(b.z, b.w);
        uint4 st = make_uint4(*(uint32_t*)&q0, *(uint32_t*)&q1,
                              *(uint32_t*)&q2, *(uint32_t*)&q3);
        *(uint4*)(smem + SM_X + swz(row, c8)) = st;
    }

    // per-thread invariant fragment coordinates
    const int arow = mwarp * 32 + (l & 15);
    const int ac8  = l >> 4;
    const int brow = nwarp * 64 + (l & 7) + ((l >> 4) << 3);
    const int bc8  = (l >> 3) & 1;

    float v1[4], v2[4], v3[4]; int i1[4], i2[4];
#pragma unroll
    for (int s = 0; s < 4; s++) { v1[s] = v2[s] = v3[s] = NEG_INF; i1[s] = 0; i2[s] = 0; }

#pragma unroll
    for (int c = 0; c < NCHK; c++) {
        if (c < 7) { CPWAIT1(); } else { CPWAIT0(); }
        __syncthreads();

        const uint32_t wb = sb + SM_W + (c & 1) * 32768;
        float acc[2][8][4];
#pragma unroll
        for (int mb = 0; mb < 2; mb++)
#pragma unroll
            for (int nb = 0; nb < 8; nb++)
#pragma unroll
                for (int e = 0; e < 4; e++) acc[mb][nb][e] = 0.f;

#pragma unroll
        for (int ks = 0; ks < 8; ks++) {
            uint32_t a[2][4], b[4][4];
#pragma unroll
            for (int mb = 0; mb < 2; mb++)
                ldm4(a[mb], sb + SM_X + swz(arow + mb * 16, ks * 2 + ac8));
#pragma unroll
            for (int p = 0; p < 4; p++)
                ldm4(b[p], wb + swz(brow + p * 16, ks * 2 + bc8));
#pragma unroll
            for (int mb = 0; mb < 2; mb++)
#pragma unroll
                for (int nb = 0; nb < 8; nb++)
                    mma16816(acc[mb][nb], a[mb],
                             b[nb >> 1][(nb & 1) * 2], b[nb >> 1][(nb & 1) * 2 + 1]);
        }

        // fold chunk into running top-3 (ascending option order; fmax prune)
        const int obase = c * NC + nwarp * 64 + 2 * (l & 3);
#pragma unroll
        for (int mb = 0; mb < 2; mb++)
#pragma unroll
            for (int rp = 0; rp < 2; rp++) {
                const int s = mb * 2 + rp;
                float m = acc[mb][0][rp * 2];
#pragma unroll
                for (int nb = 0; nb < 8; nb++) {
                    m = fmaxf(m, acc[mb][nb][rp * 2]);
                    m = fmaxf(m, acc[mb][nb][rp * 2 + 1]);
                }
                if (m > v3[s]) {
#pragma unroll
                    for (int nb = 0; nb < 8; nb++)
#pragma unroll
                        for (int e = 0; e < 2; e++) {
                            float v = acc[mb][nb][rp * 2 + e];
                            int   o = obase + nb * 8 + e;
                            if (v > v1[s]) { v3[s] = v2[s]; v2[s] = v1[s]; i2[s] = i1[s]; v1[s] = v; i1[s] = o; }
                            else if (v > v2[s]) { v3[s] = v2[s]; v2[s] = v; i2[s] = o; }
                            else if (v > v3[s]) { v3[s] = v; }
                        }
                }
            }

        __syncthreads();   // all readers of buf[c&1] done
        if (c < 6) {
            for (int i = tid; i < 2048; i += 256) {
                int row = i >> 4, c8 = i & 15;
                CP16(sb + SM_W + (c & 1) * 32768 + swz(row, c8),
                     wsrc + (size_t)((c + 2) * NC + row) * KD + c8 * 8);
            }
            CPCOMMIT();
        }
    }

    // quad-shuffle reduce, then per-(row,nwarp) table write
#pragma unroll
    for (int s = 0; s < 4; s++) {
        float a1 = v1[s], a2 = v2[s], a3 = v3[s]; int j1 = i1[s], j2 = i2[s];
#pragma unroll
        for (int off = 1; off <= 2; off <<= 1) {
            float b1 = __shfl_xor_sync(0xffffffffu, a1, off);
            float b2 = __shfl_xor_sync(0xffffffffu, a2, off);
            float b3 = __shfl_xor_sync(0xffffffffu, a3, off);
            int   k1 = __shfl_xor_sync(0xffffffffu, j1, off);
            int   k2 = __shfl_xor_sync(0xffffffffu, j2, off);
            merge3(a1, a2, a3, j1, j2, b1, b2, b3, k1, k2);
        }
        if ((l & 3) == 0) {
            int row = mwarp * 32 + (s >> 1) * 16 + (s & 1) * 8 + (l >> 2);
            int id  = nwarp * 128 + row;
            tv1[id] = a1; tv2[id] = a2; tv3[id] = a3; ti1[id] = j1; ti2[id] = j2;
        }
    }
    __syncthreads();

    if (tid < TM) {
        float a1 = tv1[tid], a2 = tv2[tid], a3 = tv3[tid];
        int   j1 = ti1[tid], j2 = ti2[tid];
        merge3(a1, a2, a3, j1, j2,
               tv1[128 + tid], tv2[128 + tid], tv3[128 + tid],
               ti1[128 + tid], ti2[128 + tid]);
        const int t = t0 + tid;
        g_idx[t * NHEADS + h] = j1;
        if (a1 - a2 <= THETA) {
            unsigned full = (a1 - a3 <= THETA) ? 0x80000000u : 0u;
            unsigned pos = atomicAdd(&g_resc_cnt, 1u);
            g_resc[pos] = make_uint2((unsigned)(t * NHEADS + h),
                                     full | (unsigned)j1 | ((unsigned)j2 << 12));
        }
    }
}

// Exact fp32 rescue for ambiguous (token,head) pairs.
__global__ void rescue_kernel(const float* __restrict__ x, const float* __restrict__ w) {
    __shared__ float xs[KD];
    __shared__ float rv[128];
    __shared__ int   ri[128];
    const unsigned cnt = g_resc_cnt;
    for (unsigned e = blockIdx.x; e < cnt; e += gridDim.x) {
        uint2 ent = g_resc[e];
        int pair = (int)ent.x;
        int t = pair / NHEADS, h = pair % NHEADS;
        unsigned bits = ent.y;
        bool full = (bits >> 31) != 0;
        int i1 = (int)(bits & 0xFFF), i2 = (int)((bits >> 12) & 0xFFF);
        __syncthreads();
        if (threadIdx.x < KD)
            xs[threadIdx.x] = x[(size_t)t * EDIM + h * KD + threadIdx.x];
        __syncthreads();
        const float* wh = w + (size_t)h * OD * KD;
        if (!full) {
            if (threadIdx.x < 32) {
                int l = threadIdx.x;
                float a1 = 0.f, a2 = 0.f;
#pragma unroll
                for (int q = 0; q < 4; q++) {
                    int k = l + 32 * q;
                    a1 += xs[k] * wh[(size_t)i1 * KD + k];
                    a2 += xs[k] * wh[(size_t)i2 * KD + k];
                }
#pragma unroll
                for (int off = 16; off; off >>= 1) {
                    a1 += __shfl_xor_sync(0xffffffffu, a1, off);
                    a2 += __shfl_xor_sync(0xffffffffu, a2, off);
                }
                if (l == 0) {
                    int best = (a2 > a1) ? i2 : ((a1 > a2) ? i1 : (i1 < i2 ? i1 : i2));
                    g_idx[pair] = best;
                }
            }
        } else {
            float bv = NEG_INF; int bi = 0;
            for (int oo = 0; oo < OD / 128; oo++) {
                int o = threadIdx.x + 128 * oo;
                float a = 0.f;
                const float* wr = wh + (size_t)o * KD;
#pragma unroll 8
                for (int k = 0; k < KD; k++) a += xs[k] * wr[k];
                if (a > bv) { bv = a; bi = o; }
            }
            rv[threadIdx.x] = bv; ri[threadIdx.x] = bi;
            __syncthreads();
            if (threadIdx.x == 0) {
                float B = rv[0]; int I = ri[0];
                for (int j = 1; j < 128; j++)
                    if (rv[j] > B || (rv[j] == B && ri[j] < I)) { B = rv[j]; I = ri[j]; }
                g_idx[pair] = I;
            }
        }
    }
}

// out[t, h*128:+128] = cb[h, idx[t,h], :]
__global__ void gather_kernel(const float* __restrict__ cb, float* __restrict__ out) {
    const float4* cb4 = (const float4*)cb;
    float4* out4 = (float4*)out;
    int q = blockIdx.x * blockDim.x + threadIdx.x;
    int t = q >> 9, r = q & 511;
    int h = r >> 5, j = r & 31;
    int bi = g_idx[t * NHEADS + h];
    out4[(size_t)t * (EDIM / 4) + h * (KD / 4) + j] =
        cb4[((size_t)h * OD + bi) * (KD / 4) + j];
}

extern "C" void kernel_launch(void* const* d_in, const int* in_sizes, int n_in,
                              void* d_out, int out_size) {
    const float* x  = (const float*)d_in[0];
    const float* w  = (const float*)d_in[1];
    const float* cb = (const float*)d_in[2];
    // d_in[3] temperature: mathematically irrelevant in the forward pass.
    float* out = (float*)d_out;

    cudaFuncSetAttribute(vq_mma_kernel,
                         cudaFuncAttributeMaxDynamicSharedMemorySize, SM_TOTAL);

    convert_w_kernel<<<(NHEADS * OD * KD / 4) / 256, 256>>>(w);
    vq_mma_kernel<<<dim3(NTOK / TM, NHEADS), 256, SM_TOTAL>>>(x);
    rescue_kernel<<<128, 128>>>(x, w);
    gather_kernel<<<(NTOK * EDIM / 4) / 256, 256>>>(cb, out);
}

// round 4
// speedup vs baseline: 1.1600x; 1.1600x over previous
#include <cuda_runtime.h>
#include <cuda_bf16.h>
#include <cstdint>

#define NHEADS 16
#define OD     1024
#define KD     128
#define NTOK   4096
#define EDIM   2048
#define TM     128        // tokens per block
#define NC     128        // options per chunk
#define NCHK   (OD/NC)    // 8
#define THETA  6e-3f
#define NEG_INF (-3.402823466e38f)

// ---------------- device scratch (allocation-free rule) ----------------
__device__ __align__(16) __nv_bfloat16 g_wb[(size_t)NHEADS * OD * KD];
__device__ int          g_idx[NTOK * NHEADS];
__device__ unsigned int g_resc_cnt;
__device__ uint2        g_resc[NTOK * NHEADS];

// ---------------- smem layout ----------------
#define SM_X    0                   // 128x128 bf16 blocked SW128 (32KB)
#define SM_W    32768               // two 32KB w buffers
#define SM_TAB  98304               // top3 tables: 5 x 256 x 4B
#define SM_TOTAL (98304 + 5120)

// ---------------- helpers ----------------
__device__ __forceinline__ uint32_t smem_u32(const void* p) {
    uint32_t a;
    asm("{ .reg .u64 t; cvta.to.shared.u64 t, %1; cvt.u32.u64 %0, t; }"
        : "=r"(a) : "l"(p));
    return a;
}

// blocked SW128 atom layout for a [128 rows x 128 bf16] tile.
// c8 = 16B vector index along k (0..15).
__device__ __forceinline__ uint32_t swz(int row, int c8) {
    uint32_t boff = (uint32_t)(((row >> 3) + (c8 >> 3) * 16) * 1024
                               + (row & 7) * 128 + (c8 & 7) * 16);
    return boff ^ ((boff >> 3) & 0x70);
}

#define CP16(dst, src) \
    asm volatile("cp.async.cg.shared.global [%0], [%1], 16;" \
        :: "r"(dst), "l"(src))
#define CPCOMMIT() asm volatile("cp.async.commit_group;" ::: "memory")
#define CPWAIT1()  asm volatile("cp.async.wait_group 1;" ::: "memory")
#define CPWAIT0()  asm volatile("cp.async.wait_group 0;" ::: "memory")

__device__ __forceinline__ void ldm4(uint32_t* r, uint32_t addr) {
    asm volatile("ldmatrix.sync.aligned.m8n8.x4.shared.b16 {%0,%1,%2,%3}, [%4];"
        : "=r"(r[0]), "=r"(r[1]), "=r"(r[2]), "=r"(r[3]) : "r"(addr));
}
__device__ __forceinline__ void mma16816(float* c, const uint32_t* a,
                                         uint32_t b0, uint32_t b1) {
    asm volatile("mma.sync.aligned.m16n8k16.row.col.f32.bf16.bf16.f32 "
        "{%0,%1,%2,%3}, {%4,%5,%6,%7}, {%8,%9}, {%0,%1,%2,%3};"
        : "+f"(c[0]), "+f"(c[1]), "+f"(c[2]), "+f"(c[3])
        : "r"(a[0]), "r"(a[1]), "r"(a[2]), "r"(a[3]), "r"(b0), "r"(b1));
}

// merge top-3 triple b into a (ties -> lower index wins)
__device__ __forceinline__ void merge3(float& a1, float& a2, float& a3, int& j1, int& j2,
                                       float b1, float b2, float b3, int k1, int k2) {
    if (b1 > a1 || (b1 == a1 && k1 < j1)) {
        float t1 = a1, t2 = a2, t3 = a3; int u1 = j1, u2 = j2;
        a1 = b1; a2 = b2; a3 = b3; j1 = k1; j2 = k2;
        b1 = t1; b2 = t2; b3 = t3; k1 = u1; k2 = u2;
    }
    if (b1 > a2 || (b1 == a2 && k1 < j2)) {
        a3 = fmaxf(a2, b2);
        a2 = b1; j2 = k1;
    } else {
        a3 = fmaxf(a3, b1);
    }
}

// ---------------- kernels ----------------

// w fp32 [h][o][k] -> bf16 (same layout); also reset rescue counter
__global__ void convert_w_kernel(const float* __restrict__ w) {
    if (blockIdx.x == 0 && threadIdx.x == 0) g_resc_cnt = 0;
    size_t i = (size_t)blockIdx.x * 256 + threadIdx.x;   // over H*O*K/4 float4s
    float4 v = ((const float4*)w)[i];
    __nv_bfloat162 q0 = __floats2bfloat162_rn(v.x, v.y);
    __nv_bfloat162 q1 = __floats2bfloat162_rn(v.z, v.w);
    uint2 st = make_uint2(*(uint32_t*)&q0, *(uint32_t*)&q1);
    *(uint2*)(g_wb + i * 4) = st;
}

// Main: block = 128 tokens x 1 head. bf16 HMMA GEMM-argmax with top-3 tracking.
// Chunk processed in two N-halves to keep accumulators at 32 regs (no spills).
__global__ __launch_bounds__(256, 2) void vq_mma_kernel(const float* __restrict__ x) {
    extern __shared__ char smem[];
    const uint32_t sb = smem_u32(smem);
    float* tv1 = (float*)(smem + SM_TAB);
    float* tv2 = tv1 + 256;
    float* tv3 = tv2 + 256;
    int*   ti1 = (int*)(tv3 + 256);
    int*   ti2 = ti1 + 256;

    const int tid = threadIdx.x, l = tid & 31, wid = tid >> 5;
    const int mwarp = wid & 3, nwarp = wid >> 2;
    const int t0 = blockIdx.x * TM, h = blockIdx.y;

    const __nv_bfloat16* wsrc = g_wb + (size_t)h * OD * KD;

    // issue w chunks 0,1 via cp.async (groups 0,1)
#pragma unroll
    for (int buf = 0; buf < 2; buf++) {
        for (int i = tid; i < 2048; i += 256) {
            int row = i >> 4, c8 = i & 15;
            CP16(sb + SM_W + buf * 32768 + swz(row, c8),
                 wsrc + (size_t)(buf * NC + row) * KD + c8 * 8);
        }
        CPCOMMIT();
    }

    // x tile: load fp32, convert to bf16, store swizzled
    for (int i = tid; i < 2048; i += 256) {
        int row = i >> 4, c8 = i & 15;
        const float4* p = (const float4*)(x + (size_t)(t0 + row) * EDIM + h * KD + c8 * 8);
        float4 a = p[0], b = p[1];
        __nv_bfloat162 q0 = __floats2bfloat162_rn(a.x, a.y);
        __nv_bfloat162 q1 = __floats2bfloat162_rn(a.z, a.w);
        __nv_bfloat162 q2 = __floats2bfloat162_rn(b.x, b.y);
        __nv_bfloat162 q3 = __floats2bfloat162_rn(b.z, b.w);
        uint4 st = make_uint4(*(uint32_t*)&q0, *(uint32_t*)&q1,
                              *(uint32_t*)&q2, *(uint32_t*)&q3);
        *(uint4*)(smem + SM_X + swz(row, c8)) = st;
    }

    // per-thread invariant fragment coordinates
    const int arow = mwarp * 32 + (l & 15);
    const int ac8  = l >> 4;
    const int brow = nwarp * 64 + (l & 7) + ((l >> 4) << 3);
    const int bc8  = (l >> 3) & 1;

    float v1[4], v2[4], v3[4]; int i1[4], i2[4];
#pragma unroll
    for (int s = 0; s < 4; s++) { v1[s] = v2[s] = v3[s] = NEG_INF; i1[s] = 0; i2[s] = 0; }

#pragma unroll 1
    for (int c = 0; c < NCHK; c++) {
        if (c < 7) { CPWAIT1(); } else { CPWAIT0(); }
        __syncthreads();

        const uint32_t wb = sb + SM_W + (c & 1) * 32768;

#pragma unroll 1
        for (int half = 0; half < 2; half++) {
            float acc[2][4][4];
#pragma unroll
            for (int mb = 0; mb < 2; mb++)
#pragma unroll
                for (int nb = 0; nb < 4; nb++)
#pragma unroll
                    for (int e = 0; e < 4; e++) acc[mb][nb][e] = 0.f;

#pragma unroll
            for (int ks = 0; ks < 8; ks++) {
                uint32_t a[2][4], b[2][4];
#pragma unroll
                for (int mb = 0; mb < 2; mb++)
                    ldm4(a[mb], sb + SM_X + swz(arow + mb * 16, ks * 2 + ac8));
#pragma unroll
                for (int q = 0; q < 2; q++)
                    ldm4(b[q], wb + swz(brow + (half * 2 + q) * 16, ks * 2 + bc8));
#pragma unroll
                for (int mb = 0; mb < 2; mb++)
#pragma unroll
                    for (int nb = 0; nb < 4; nb++)
                        mma16816(acc[mb][nb], a[mb],
                                 b[nb >> 1][(nb & 1) * 2], b[nb >> 1][(nb & 1) * 2 + 1]);
            }

            // fold half-chunk into running top-3 (ascending option order; fmax prune)
            const int obase = c * NC + nwarp * 64 + 2 * (l & 3);
#pragma unroll
            for (int mb = 0; mb < 2; mb++)
#pragma unroll
                for (int rp = 0; rp < 2; rp++) {
                    const int s = mb * 2 + rp;
                    float m = acc[mb][0][rp * 2];
#pragma unroll
                    for (int nb = 0; nb < 4; nb++) {
                        m = fmaxf(m, acc[mb][nb][rp * 2]);
                        m = fmaxf(m, acc[mb][nb][rp * 2 + 1]);
                    }
                    if (m > v3[s]) {
#pragma unroll
                        for (int nb = 0; nb < 4; nb++)
#pragma unroll
                            for (int e = 0; e < 2; e++) {
                                float v = acc[mb][nb][rp * 2 + e];
                                int   o = obase + (half * 4 + nb) * 8 + e;
                                if (v > v1[s]) { v3[s] = v2[s]; v2[s] = v1[s]; i2[s] = i1[s]; v1[s] = v; i1[s] = o; }
                                else if (v > v2[s]) { v3[s] = v2[s]; v2[s] = v; i2[s] = o; }
                                else if (v > v3[s]) { v3[s] = v; }
                            }
                    }
                }
        }

        __syncthreads();   // all readers of buf[c&1] done
        if (c < 6) {
            for (int i = tid; i < 2048; i += 256) {
                int row = i >> 4, c8 = i & 15;
                CP16(sb + SM_W + (c & 1) * 32768 + swz(row, c8),
                     wsrc + (size_t)((c + 2) * NC + row) * KD + c8 * 8);
            }
            CPCOMMIT();
        }
    }

    // quad-shuffle reduce, then per-(row,nwarp) table write
#pragma unroll
    for (int s = 0; s < 4; s++) {
        float a1 = v1[s], a2 = v2[s], a3 = v3[s]; int j1 = i1[s], j2 = i2[s];
#pragma unroll
        for (int off = 1; off <= 2; off <<= 1) {
            float b1 = __shfl_xor_sync(0xffffffffu, a1, off);
            float b2 = __shfl_xor_sync(0xffffffffu, a2, off);
            float b3 = __shfl_xor_sync(0xffffffffu, a3, off);
            int   k1 = __shfl_xor_sync(0xffffffffu, j1, off);
            int   k2 = __shfl_xor_sync(0xffffffffu, j2, off);
            merge3(a1, a2, a3, j1, j2, b1, b2, b3, k1, k2);
        }
        if ((l & 3) == 0) {
            int row = mwarp * 32 + (s >> 1) * 16 + (s & 1) * 8 + (l >> 2);
            int id  = nwarp * 128 + row;
            tv1[id] = a1; tv2[id] = a2; tv3[id] = a3; ti1[id] = j1; ti2[id] = j2;
        }
    }
    __syncthreads();

    if (tid < TM) {
        float a1 = tv1[tid], a2 = tv2[tid], a3 = tv3[tid];
        int   j1 = ti1[tid], j2 = ti2[tid];
        merge3(a1, a2, a3, j1, j2,
               tv1[128 + tid], tv2[128 + tid], tv3[128 + tid],
               ti1[128 + tid], ti2[128 + tid]);
        const int t = t0 + tid;
        g_idx[t * NHEADS + h] = j1;
        if (a1 - a2 <= THETA) {
            unsigned full = (a1 - a3 <= THETA) ? 0x80000000u : 0u;
            unsigned pos = atomicAdd(&g_resc_cnt, 1u);
            g_resc[pos] = make_uint2((unsigned)(t * NHEADS + h),
                                     full | (unsigned)j1 | ((unsigned)j2 << 12));
        }
    }
}

// Exact fp32 rescue for ambiguous (token,head) pairs.
__global__ void rescue_kernel(const float* __restrict__ x, const float* __restrict__ w) {
    __shared__ float xs[KD];
    __shared__ float rv[128];
    __shared__ int   ri[128];
    const unsigned cnt = g_resc_cnt;
    for (unsigned e = blockIdx.x; e < cnt; e += gridDim.x) {
        uint2 ent = g_resc[e];
        int pair = (int)ent.x;
        int t = pair / NHEADS, h = pair % NHEADS;
        unsigned bits = ent.y;
        bool full = (bits >> 31) != 0;
        int i1 = (int)(bits & 0xFFF), i2 = (int)((bits >> 12) & 0xFFF);
        __syncthreads();
        if (threadIdx.x < KD)
            xs[threadIdx.x] = x[(size_t)t * EDIM + h * KD + threadIdx.x];
        __syncthreads();
        const float* wh = w + (size_t)h * OD * KD;
        if (!full) {
            if (threadIdx.x < 32) {
                int l = threadIdx.x;
                float a1 = 0.f, a2 = 0.f;
#pragma unroll
                for (int q = 0; q < 4; q++) {
                    int k = l + 32 * q;
                    a1 += xs[k] * wh[(size_t)i1 * KD + k];
                    a2 += xs[k] * wh[(size_t)i2 * KD + k];
                }
#pragma unroll
                for (int off = 16; off; off >>= 1) {
                    a1 += __shfl_xor_sync(0xffffffffu, a1, off);
                    a2 += __shfl_xor_sync(0xffffffffu, a2, off);
                }
                if (l == 0) {
                    int best = (a2 > a1) ? i2 : ((a1 > a2) ? i1 : (i1 < i2 ? i1 : i2));
                    g_idx[pair] = best;
                }
            }
        } else {
            float bv = NEG_INF; int bi = 0;
            for (int oo = 0; oo < OD / 128; oo++) {
                int o = threadIdx.x + 128 * oo;
                float a = 0.f;
                const float* wr = wh + (size_t)o * KD;
#pragma unroll 8
                for (int k = 0; k < KD; k++) a += xs[k] * wr[k];
                if (a > bv) { bv = a; bi = o; }
            }
            rv[threadIdx.x] = bv; ri[threadIdx.x] = bi;
            __syncthreads();
            if (threadIdx.x == 0) {
                float B = rv[0]; int I = ri[0];
                for (int j = 1; j < 128; j++)
                    if (rv[j] > B || (rv[j] == B && ri[j] < I)) { B = rv[j]; I = ri[j]; }
                g_idx[pair] = I;
            }
        }
    }
}

// out[t, h*128:+128] = cb[h, idx[t,h], :]
__global__ void gather_kernel(const float* __restrict__ cb, float* __restrict__ out) {
    const float4* cb4 = (const float4*)cb;
    float4* out4 = (float4*)out;
    int q = blockIdx.x * blockDim.x + threadIdx.x;
    int t = q >> 9, r = q & 511;
    int h = r >> 5, j = r & 31;
    int bi = g_idx[t * NHEADS + h];
    out4[(size_t)t * (EDIM / 4) + h * (KD / 4) + j] =
        cb4[((size_t)h * OD + bi) * (KD / 4) + j];
}

extern "C" void kernel_launch(void* const* d_in, const int* in_sizes, int n_in,
                              void* d_out, int out_size) {
    const float* x  = (const float*)d_in[0];
    const float* w  = (const float*)d_in[1];
    const float* cb = (const float*)d_in[2];
    // d_in[3] temperature: mathematically irrelevant in the forward pass.
    float* out = (float*)d_out;

    cudaFuncSetAttribute(vq_mma_kernel,
                         cudaFuncAttributeMaxDynamicSharedMemorySize, SM_TOTAL);

    convert_w_kernel<<<(NHEADS * OD * KD / 4) / 256, 256>>>(w);
    vq_mma_kernel<<<dim3(NTOK / TM, NHEADS), 256, SM_TOTAL>>>(x);
    rescue_kernel<<<128, 128>>>(x, w);
    gather_kernel<<<(NTOK * EDIM / 4) / 256, 256>>>(cb, out);
}

// round 5
// speedup vs baseline: 1.5408x; 1.3283x over previous
#include <cuda_runtime.h>
#include <cstdint>

#define NHEADS 16
#define OD     1024
#define KD     128
#define NK4    (KD/4)     // 32
#define NTOK   4096
#define EDIM   2048
#define TM     64         // tokens per main block
#define NC     128        // options per chunk
#define NCHK   (OD/NC)    // 8
#define THETA  0.032f
#define NEG_INF (-3.402823466e38f)
#define R2CAP  1024

// ---------------- device scratch (allocation-free rule) ----------------
__device__ __align__(16) int   g_xq[NHEADS*NK4*NTOK];   // [h][k4][t]
__device__ __align__(16) int   g_wq[NHEADS*NK4*OD];     // [h][k4][o]
__device__ __align__(16) float g_sx[NHEADS*NTOK];
__device__ __align__(16) float g_sw[NHEADS*OD];
__device__ int      g_idx[NTOK*NHEADS];
__device__ unsigned g_r1n;
__device__ uint2    g_r1[NTOK*NHEADS];
__device__ unsigned g_r2n[NHEADS];
__device__ int      g_r2[NHEADS][R2CAP];

// ---------------- helpers ----------------
#define CP16(dst, src) \
    asm volatile("cp.async.cg.shared.global [%0], [%1], 16;" :: "r"(dst), "l"(src))
#define CPCOMMIT() asm volatile("cp.async.commit_group;" ::: "memory")
#define CPWAIT1()  asm volatile("cp.async.wait_group 1;" ::: "memory")
#define CPWAIT0()  asm volatile("cp.async.wait_group 0;" ::: "memory")

__device__ __forceinline__ uint32_t smem_u32(const void* p) {
    uint32_t a;
    asm("{ .reg .u64 t; cvta.to.shared.u64 t, %1; cvt.u32.u64 %0, t; }" : "=r"(a) : "l"(p));
    return a;
}
__device__ __forceinline__ int q8(float v, float inv) {
    int a = __float2int_rn(v * inv);
    return a < -127 ? -127 : (a > 127 ? 127 : a);
}

// merge top-3 triple b into a (ties -> lower index wins)
__device__ __forceinline__ void merge3(float& a1, float& a2, float& a3, int& j1, int& j2,
                                       float b1, float b2, float b3, int k1, int k2) {
    if (b1 > a1 || (b1 == a1 && k1 < j1)) {
        float t1 = a1, t2 = a2, t3 = a3; int u1 = j1, u2 = j2;
        a1 = b1; a2 = b2; a3 = b3; j1 = k1; j2 = k2;
        b1 = t1; b2 = t2; b3 = t3; k1 = u1; k2 = u2;
    }
    if (b1 > a2 || (b1 == a2 && k1 < j2)) { a3 = fmaxf(a2, b2); a2 = b1; j2 = k1; }
    else                                  { a3 = fmaxf(a3, b1); }
}

// ---------------- quantization kernels ----------------
// 32 rows of 128 floats per block; transpose to [k4][row] packed-int8 layout.
template<int NROW_TOT>
__device__ __forceinline__ void quant_rows(const float* __restrict__ src_base, size_t row_stride,
                                           int* __restrict__ dst, float* __restrict__ scale_out,
                                           int r0) {
    __shared__ int   trans[32 * 33];
    __shared__ float sxs[32];
    const int tid = threadIdx.x, l = tid & 31, wid = tid >> 5;
    for (int r = wid; r < 32; r += 8) {
        float4 v = *(const float4*)(src_base + (size_t)(r0 + r) * row_stride + l * 4);
        float mx = fmaxf(fmaxf(fabsf(v.x), fabsf(v.y)), fmaxf(fabsf(v.z), fabsf(v.w)));
#pragma unroll
        for (int off = 16; off; off >>= 1)
            mx = fmaxf(mx, __shfl_xor_sync(0xffffffffu, mx, off));
        float inv = (mx > 0.f) ? 127.f / mx : 0.f;
        int a0 = q8(v.x, inv), a1 = q8(v.y, inv), a2 = q8(v.z, inv), a3 = q8(v.w, inv);
        trans[l * 33 + r] = (a0 & 255) | ((a1 & 255) << 8) | ((a2 & 255) << 16) | ((a3 & 255) << 24);
        if (l == 0) sxs[r] = mx * (1.f / 127.f);
    }
    __syncthreads();
    for (int i = tid; i < 1024; i += 256) {
        int k4 = i >> 5, rl = i & 31;
        dst[k4 * NROW_TOT + r0 + rl] = trans[k4 * 33 + rl];
    }
    if (tid < 32) scale_out[r0 + tid] = sxs[tid];
}

__global__ __launch_bounds__(256) void quant_x_kernel(const float* __restrict__ x) {
    const int h = blockIdx.y, t0 = blockIdx.x * 32;
    quant_rows<NTOK>(x + h * KD, EDIM, g_xq + h * NK4 * NTOK, g_sx + h * NTOK, t0);
}

__global__ __launch_bounds__(256) void quant_w_kernel(const float* __restrict__ w) {
    if (blockIdx.x == 0 && blockIdx.y == 0) {
        if (threadIdx.x == 0) g_r1n = 0;
        if (threadIdx.x < NHEADS) g_r2n[threadIdx.x] = 0;
    }
    const int h = blockIdx.y, o0 = blockIdx.x * 32;
    quant_rows<OD>(w + (size_t)h * OD * KD, KD, g_wq + h * NK4 * OD, g_sw + h * OD, o0);
}

// ---------------- main dp4a GEMM-argmax ----------------
// block = 64 tokens x 1 head; 256 threads = 16 tx (8 options each) x 16 ty (4 tokens each)
__global__ __launch_bounds__(256, 2) void vq_dp4a_kernel() {
    __shared__ __align__(16) int   Xs[NK4][TM];          // 8KB
    __shared__ __align__(16) int   Ws[2][NK4][NC];       // 32KB
    __shared__ __align__(16) float sws[2][NC];           // 1KB

    const int tid = threadIdx.x;
    const int tx = tid & 15, ty = tid >> 4;
    const int t0 = blockIdx.x * TM, h = blockIdx.y;

    const uint32_t xs_a = smem_u32(Xs), ws_a = smem_u32(Ws), sw_a = smem_u32(sws);
    const int* xsrc = g_xq + (size_t)h * NK4 * NTOK;
    const int* wsrc = g_wq + (size_t)h * NK4 * OD;
    const float* swsrc = g_sw + (size_t)h * OD;

    // group 0: x tile + w chunk 0 + sw 0; group 1: w chunk 1 + sw 1
#pragma unroll
    for (int r = 0; r < 2; r++) {
        int i = tid + 256 * r;
        int k4 = i >> 4, seg = i & 15;
        CP16(xs_a + (k4 * TM + seg * 4) * 4, xsrc + (size_t)k4 * NTOK + t0 + seg * 4);
    }
#pragma unroll
    for (int buf = 0; buf < 2; buf++) {
#pragma unroll
        for (int r = 0; r < 4; r++) {
            int i = tid + 256 * r;
            int k4 = i >> 5, seg = i & 31;
            CP16(ws_a + ((buf * NK4 + k4) * NC + seg * 4) * 4,
                 wsrc + (size_t)k4 * OD + buf * NC + seg * 4);
        }
        if (tid < 32)
            CP16(sw_a + (buf * NC + tid * 4) * 4, swsrc + buf * NC + tid * 4);
        CPCOMMIT();
    }

    float v1[4], v2[4], v3[4]; int i1[4], i2[4];
#pragma unroll
    for (int p = 0; p < 4; p++) { v1[p] = v2[p] = v3[p] = NEG_INF; i1[p] = 0; i2[p] = 0; }

#pragma unroll 1
    for (int c = 0; c < NCHK; c++) {
        if (c < NCHK - 1) { CPWAIT1(); } else { CPWAIT0(); }
        __syncthreads();
        const int buf = c & 1;

        int acc[4][8];
#pragma unroll
        for (int p = 0; p < 4; p++)
#pragma unroll
            for (int u = 0; u < 8; u++) acc[p][u] = 0;

#pragma unroll 8
        for (int k4 = 0; k4 < NK4; k4++) {
            int4 xv = *(const int4*)&Xs[k4][ty * 4];
            int4 wa = *(const int4*)&Ws[buf][k4][tx * 8];
            int4 wb = *(const int4*)&Ws[buf][k4][tx * 8 + 4];
            const int wr[8] = { wa.x, wa.y, wa.z, wa.w, wb.x, wb.y, wb.z, wb.w };
            const int xr[4] = { xv.x, xv.y, xv.z, xv.w };
#pragma unroll
            for (int p = 0; p < 4; p++)
#pragma unroll
                for (int u = 0; u < 8; u++)
                    acc[p][u] = __dp4a(xr[p], wr[u], acc[p][u]);
        }

        // fold: q = sw_o * (float)acc   (sx common factor applied at the end)
        float4 s0 = *(const float4*)&sws[buf][tx * 8];
        float4 s1 = *(const float4*)&sws[buf][tx * 8 + 4];
        const float sv[8] = { s0.x, s0.y, s0.z, s0.w, s1.x, s1.y, s1.z, s1.w };
        const int obase = c * NC + tx * 8;
#pragma unroll
        for (int p = 0; p < 4; p++) {
            float q[8];
#pragma unroll
            for (int u = 0; u < 8; u++) q[u] = (float)acc[p][u] * sv[u];
            float m = q[0];
#pragma unroll
            for (int u = 1; u < 8; u++) m = fmaxf(m, q[u]);
            if (m > v3[p]) {
#pragma unroll
                for (int u = 0; u < 8; u++) {
                    float v = q[u]; int o = obase + u;
                    if (v > v1[p]) { v3[p] = v2[p]; v2[p] = v1[p]; i2[p] = i1[p]; v1[p] = v; i1[p] = o; }
                    else if (v > v2[p]) { v3[p] = v2[p]; v2[p] = v; i2[p] = o; }
                    else if (v > v3[p]) { v3[p] = v; }
                }
            }
        }

        __syncthreads();
        if (c < NCHK - 2) {
#pragma unroll
            for (int r = 0; r < 4; r++) {
                int i = tid + 256 * r;
                int k4 = i >> 5, seg = i & 31;
                CP16(ws_a + ((buf * NK4 + k4) * NC + seg * 4) * 4,
                     wsrc + (size_t)k4 * OD + (c + 2) * NC + seg * 4);
            }
            if (tid < 32)
                CP16(sw_a + (buf * NC + tid * 4) * 4, swsrc + (c + 2) * NC + tid * 4);
            CPCOMMIT();
        }
    }

    // reduce across the 16 option-lanes (tokens identical within each 16-lane group)
#pragma unroll
    for (int p = 0; p < 4; p++) {
        float a1 = v1[p], a2 = v2[p], a3 = v3[p]; int j1 = i1[p], j2 = i2[p];
#pragma unroll
        for (int off = 1; off <= 8; off <<= 1) {
            float b1 = __shfl_xor_sync(0xffffffffu, a1, off);
            float b2 = __shfl_xor_sync(0xffffffffu, a2, off);
            float b3 = __shfl_xor_sync(0xffffffffu, a3, off);
            int   k1 = __shfl_xor_sync(0xffffffffu, j1, off);
            int   k2 = __shfl_xor_sync(0xffffffffu, j2, off);
            merge3(a1, a2, a3, j1, j2, b1, b2, b3, k1, k2);
        }
        if ((tid & 15) == 0) {
            const int t = t0 + ty * 4 + p;
            g_idx[t * NHEADS + h] = j1;
            const float sx = g_sx[h * NTOK + t];
            if ((a1 - a3) * sx <= THETA) {
                unsigned q = atomicAdd(&g_r2n[h], 1u);
                if (q < R2CAP) g_r2[h][q] = t;
            } else if ((a1 - a2) * sx <= THETA) {
                unsigned q = atomicAdd(&g_r1n, 1u);
                g_r1[q] = make_uint2((unsigned)(t * NHEADS + h),
                                     (unsigned)j1 | ((unsigned)j2 << 12));
            }
        }
    }
}

// ---------------- tier-1 rescue: exact fp32 2-dot compare ----------------
__global__ __launch_bounds__(256) void rescue1_kernel(const float* __restrict__ x,
                                                      const float* __restrict__ w) {
    const unsigned cnt = g_r1n;
    const int l = threadIdx.x & 31;
    const int gw = (blockIdx.x * 256 + threadIdx.x) >> 5;
    for (unsigned e = gw; e < cnt; e += 2048) {
        uint2 ent = g_r1[e];
        int pair = (int)ent.x, t = pair >> 4, h = pair & 15;
        int i1 = (int)(ent.y & 0xFFF), i2 = (int)((ent.y >> 12) & 0xFFF);
        float4 xv = ((const float4*)(x + (size_t)t * EDIM + h * KD))[l];
        float4 w1 = ((const float4*)(w + ((size_t)h * OD + i1) * KD))[l];
        float4 w2 = ((const float4*)(w + ((size_t)h * OD + i2) * KD))[l];
        float a1 = xv.x * w1.x + xv.y * w1.y + xv.z * w1.z + xv.w * w1.w;
        float a2 = xv.x * w2.x + xv.y * w2.y + xv.z * w2.z + xv.w * w2.w;
#pragma unroll
        for (int off = 16; off; off >>= 1) {
            a1 += __shfl_xor_sync(0xffffffffu, a1, off);
            a2 += __shfl_xor_sync(0xffffffffu, a2, off);
        }
        if (l == 0)
            g_idx[pair] = (a2 > a1) ? i2 : ((a1 > a2) ? i1 : (i1 < i2 ? i1 : i2));
    }
}

// ---------------- tier-2 rescue: batched exact full recompute ----------------
// block = (head, batch of 8 tokens); streams w through smem in 64-option chunks
__global__ __launch_bounds__(256) void rescue2_kernel(const float* __restrict__ x,
                                                      const float* __restrict__ w) {
    __shared__ __align__(16) float xs[8][128];
    __shared__ __align__(16) float ws[64][128];
    __shared__ int   toks[8];
    __shared__ float rv[8][2];
    __shared__ int   ri[8][2];

    const int h = blockIdx.x;
    unsigned n = g_r2n[h]; if (n > R2CAP) n = R2CAP;
    const unsigned b0 = blockIdx.y * 8;
    if (b0 >= n) return;
    const int cnt = (int)((n - b0 < 8) ? (n - b0) : 8);
    const int tid = threadIdx.x, ol = tid & 63, tg = tid >> 6;

    if (tid < cnt) toks[tid] = g_r2[h][b0 + tid];
    __syncthreads();
    for (int i = tid; i < cnt * 32; i += 256) {
        int e = i >> 5, k4 = i & 31;
        ((float4*)xs[e])[k4] = ((const float4*)(x + (size_t)toks[e] * EDIM + h * KD))[k4];
    }

    float bv[2] = { NEG_INF, NEG_INF };
    int   bi[2] = { 0, 0 };

    for (int c = 0; c < 16; c++) {
        __syncthreads();
        for (int i = tid; i < 2048; i += 256) {
            int row = i >> 5, k4 = i & 31;
            ((float4*)ws[row])[k4] =
                ((const float4*)(w + ((size_t)h * OD + c * 64 + row) * KD))[k4];
        }
        __syncthreads();
#pragma unroll
        for (int j = 0; j < 2; j++) {
            int e = tg * 2 + j;
            if (e < cnt) {
                float d = 0.f;
#pragma unroll 8
                for (int k4 = 0; k4 < 32; k4++) {
                    int kk = (k4 + ol) & 31;   // rotate to avoid 32-way bank conflict
                    float4 a = ((const float4*)xs[e])[kk];
                    float4 b = ((const float4*)ws[ol])[kk];
                    d += a.x * b.x + a.y * b.y + a.z * b.z + a.w * b.w;
                }
                int o = c * 64 + ol;
                if (d > bv[j] ) { bv[j] = d; bi[j] = o; }
            }
        }
    }

    // reduce across the 64 threads (2 warps) per token group
#pragma unroll
    for (int j = 0; j < 2; j++) {
        float v = bv[j]; int id = bi[j];
#pragma unroll
        for (int off = 16; off; off >>= 1) {
            float v2 = __shfl_xor_sync(0xffffffffu, v, off);
            int   d2 = __shfl_xor_sync(0xffffffffu, id, off);
            if (v2 > v || (v2 == v && d2 < id)) { v = v2; id = d2; }
        }
        if ((tid & 31) == 0) {
            int e = tg * 2 + j;
            rv[e][(tid >> 5) & 1] = v;
            ri[e][(tid >> 5) & 1] = id;
        }
    }
    __syncthreads();
    if (tid < cnt) {
        float a = rv[tid][0], b = rv[tid][1];
        int ia = ri[tid][0], ib = ri[tid][1];
        int best = (b > a || (b == a && ib < ia)) ? ib : ia;
        g_idx[toks[tid] * NHEADS + h] = best;
    }
}

// ---------------- gather ----------------
__global__ __launch_bounds__(256) void gather_kernel(const float* __restrict__ cb,
                                                     float* __restrict__ out) {
    const float4* cb4 = (const float4*)cb;
    float4* out4 = (float4*)out;
    int q = blockIdx.x * blockDim.x + threadIdx.x;
    int t = q >> 9, r = q & 511;
    int h = r >> 5, j = r & 31;
    int bi = g_idx[t * NHEADS + h];
    out4[(size_t)t * (EDIM / 4) + h * (KD / 4) + j] =
        cb4[((size_t)h * OD + bi) * (KD / 4) + j];
}

extern "C" void kernel_launch(void* const* d_in, const int* in_sizes, int n_in,
                              void* d_out, int out_size) {
    const float* x  = (const float*)d_in[0];
    const float* w  = (const float*)d_in[1];
    const float* cb = (const float*)d_in[2];
    // d_in[3] temperature: mathematically irrelevant in the forward pass.
    float* out = (float*)d_out;

    quant_x_kernel<<<dim3(NTOK / 32, NHEADS), 256>>>(x);
    quant_w_kernel<<<dim3(OD / 32, NHEADS), 256>>>(w);
    vq_dp4a_kernel<<<dim3(NTOK / TM, NHEADS), 256>>>();
    rescue1_kernel<<<256, 256>>>(x, w);
    rescue2_kernel<<<dim3(NHEADS, R2CAP / 8), 256>>>(x, w);
    gather_kernel<<<(NTOK * EDIM / 4) / 256, 256>>>(cb, out);
}